// round 17
// baseline (speedup 1.0000x reference)
#include <cuda_runtime.h>
#include <cuda_fp16.h>
#include <cstdint>

#define NODES  262144
#define H      256
#define NGRAPH 4096
#define NCHUNK 128

// ---- tiling: cluster of 2 CTAs shares 128 rows; each CTA: TN=128 cols ----
#define TM   128
#define TN   128
#define BK   32
#define NKC  (H / BK)   // 8

// padded fp16 row: 32 halves + 8 pad = 80 B (conflict-free LDSM)
#define ROWB     80
// SMEM map (per CTA)
#define XS_CH(c)   ((c) * 10240)               // 8 chunks x (128 rows x 80B) = 81920
#define WSB(i)     (81920 + (i) * 10240)       // 2 stages x (128 rows x 80B) = 20480
#define SC_OFF     102400                      // 128 f32 partial scores
#define E16_OFF    (SC_OFF + 512)              // 128 fp16 e
#define ES_OFF     (E16_OFF + 256)             // 2 f32 graph e-sums
#define B1_OFF     (ES_OFF + 16)               // 128 f32 (this CTA's cols)
#define W2S_OFF    (B1_OFF + 512)              // 128 f32
#define SMEM_TOTAL (W2S_OFF + 512)             // 103936 -> 2 CTAs/SM

// ---------------- scratch ----------------
__device__ float d_gsum[NGRAPH];
__device__ __align__(16) __half d_W1T[H * H];  // [n][k] fp16

// ---------------- helpers ----------------
__device__ __forceinline__ uint32_t smem_u32(const void* p) {
    uint32_t a;
    asm("{ .reg .u64 t; cvta.to.shared.u64 t, %1; cvt.u32.u64 %0, t; }"
        : "=r"(a) : "l"(p));
    return a;
}
__device__ __forceinline__ void cp_async16(uint32_t dst, const void* src) {
    asm volatile("cp.async.cg.shared.global [%0], [%1], 16;"
                 :: "r"(dst), "l"(src) : "memory");
}
__device__ __forceinline__ uint32_t f16pack(float a, float b) {
    uint32_t r;
    asm("cvt.rn.f16x2.f32 %0, %1, %2;" : "=r"(r) : "f"(b), "f"(a));
    return r;
}
__device__ __forceinline__ float fast_tanh(float x) {
    float p = fminf(fmaxf(x, -15.f), 15.f);
    float e = __expf(2.f * p);
    return __fdividef(e - 1.f, e + 1.f);
}
__device__ __forceinline__ void ldsm4(uint32_t* r, uint32_t addr) {
    asm volatile("ldmatrix.sync.aligned.m8n8.x4.shared.b16 {%0,%1,%2,%3}, [%4];"
                 : "=r"(r[0]), "=r"(r[1]), "=r"(r[2]), "=r"(r[3]) : "r"(addr));
}
__device__ __forceinline__ void ldsm4t(uint32_t* r, uint32_t addr) {
    asm volatile("ldmatrix.sync.aligned.m8n8.x4.trans.shared.b16 {%0,%1,%2,%3}, [%4];"
                 : "=r"(r[0]), "=r"(r[1]), "=r"(r[2]), "=r"(r[3]) : "r"(addr));
}
__device__ __forceinline__ float dsmem_ld_f32(uint32_t local_addr, uint32_t rank) {
    uint32_t ra; float v;
    asm("mapa.shared::cluster.u32 %0, %1, %2;" : "=r"(ra) : "r"(local_addr), "r"(rank));
    asm volatile("ld.shared::cluster.f32 %0, [%1];" : "=f"(v) : "r"(ra));
    return v;
}
#define CLUSTER_SYNC() do {                                                    \
    asm volatile("barrier.cluster.arrive.aligned;" ::: "memory");              \
    asm volatile("barrier.cluster.wait.aligned;" ::: "memory");                \
} while (0)
#define MMA_F16(c, a0, a1, a2, a3, b0, b1)                                     \
    asm volatile(                                                              \
        "mma.sync.aligned.m16n8k16.row.col.f32.f16.f16.f32 "                   \
        "{%0,%1,%2,%3}, {%4,%5,%6,%7}, {%8,%9}, {%0,%1,%2,%3};"                \
        : "+f"(c[0]), "+f"(c[1]), "+f"(c[2]), "+f"(c[3])                       \
        : "r"(a0), "r"(a1), "r"(a2), "r"(a3), "r"(b0), "r"(b1))

// ---------------- W1 fp16 + transpose ----------------
__global__ void prep_w_kernel(const float* __restrict__ W1)
{
    int k = blockIdx.x, n = threadIdx.x;
    d_W1T[n * H + k] = __float2half_rn(W1[k * H + n]);
}

// ===== cluster-pair mega kernel =====
extern __shared__ __align__(16) char smem[];

__global__ void __launch_bounds__(256, 2) __cluster_dims__(2, 1, 1)
mega_kernel(const float* __restrict__ x, const float* __restrict__ b1,
            const float* __restrict__ W2, float* __restrict__ out)
{
    const int tid = threadIdx.x;
    const int warp = tid >> 5, lane = tid & 31;
    const int g = lane >> 2, t = lane & 3;
    const int warp_m = warp & 1;    // 0..1 : 64 rows
    const int warp_n = warp >> 1;   // 0..3 : 32 cols
    const int row0 = (blockIdx.x >> 1) * TM;
    const int rank = blockIdx.x & 1;            // cluster CTA rank
    const int col_base = rank * TN;
    const int gbase = (blockIdx.x >> 1) * 2;    // 2 graphs per 128 rows

    float* score_s = (float*)(smem + SC_OFF);
    __half* e16    = (__half*)(smem + E16_OFF);
    float* esum    = (float*)(smem + ES_OFF);
    float* b1s     = (float*)(smem + B1_OFF);
    float* w2s     = (float*)(smem + W2S_OFF);
    const uint32_t sb = smem_u32(smem);

    if (tid < 128) {
        score_s[tid] = 0.f;
        b1s[tid] = b1[col_base + tid];
        w2s[tid] = W2[col_base + tid];
    }
    if (tid < 2) esum[tid] = 0.f;

    // x-load mapping: thread = (row, half): 16 floats/stage
    const int r  = tid >> 1;
    const int hf = tid & 1;
    const float* gx = x + (size_t)(row0 + r) * H + hf * 16;
    const uint32_t doff = (uint32_t)r * ROWB + (uint32_t)hf * 32;
    // W-load mapping: same thread shape over this CTA's 128 W rows
    const __half* gW = d_W1T + (size_t)(col_base + r) * H + hf * 16;

    const uint32_t lrow  = lane & 15;
    const uint32_t lhalf = (lane >> 4) * 16;
    uint32_t aBase[4], bBase[2];
#pragma unroll
    for (int mf = 0; mf < 4; ++mf)
        aBase[mf] = (uint32_t)(warp_m * 64 + mf * 16 + lrow) * ROWB + lhalf;
#pragma unroll
    for (int p = 0; p < 2; ++p)
        bBase[p] = (uint32_t)(warp_n * 32 + p * 16 + lrow) * ROWB + lhalf;

    float acc[4][4][4];
#pragma unroll
    for (int a = 0; a < 4; ++a)
#pragma unroll
        for (int b = 0; b < 4; ++b)
#pragma unroll
            for (int c = 0; c < 4; ++c) acc[a][b][c] = 0.f;

    // ---- prologue: stage 0 ----
    {
        cp_async16(sb + WSB(0) + doff,      gW);
        cp_async16(sb + WSB(0) + doff + 16, gW + 8);
        asm volatile("cp.async.commit_group;" ::: "memory");

        float4 a0 = ((const float4*)gx)[0];
        float4 a1 = ((const float4*)gx)[1];
        float4 a2 = ((const float4*)gx)[2];
        float4 a3 = ((const float4*)gx)[3];
        uint32_t h0 = f16pack(a0.x, a0.y), h1 = f16pack(a0.z, a0.w);
        uint32_t h2 = f16pack(a1.x, a1.y), h3 = f16pack(a1.z, a1.w);
        uint32_t h4 = f16pack(a2.x, a2.y), h5 = f16pack(a2.z, a2.w);
        uint32_t h6 = f16pack(a3.x, a3.y), h7 = f16pack(a3.z, a3.w);
        // note: hf selects 16-float half of BK=32 -> both halves of chunk 0 row
        *(uint4*)(smem + XS_CH(0) + doff)      = make_uint4(h0, h1, h2, h3);
        *(uint4*)(smem + XS_CH(0) + doff + 16) = make_uint4(h4, h5, h6, h7);

        asm volatile("cp.async.wait_group 0;" ::: "memory");
    }
    __syncthreads();

    // ---- main loop ----
#pragma unroll
    for (int kc = 0; kc < NKC; ++kc) {
        const bool has_next = (kc + 1) < NKC;
        const uint32_t sx = sb + XS_CH(kc);
        const uint32_t sw = sb + WSB(kc & 1);
        float4 av[4];

        if (has_next) {
            const int k1 = (kc + 1) * BK;
            const float4* ap = (const float4*)(gx + k1);
#pragma unroll
            for (int j = 0; j < 4; ++j) av[j] = ap[j];
            const uint32_t wd = sb + WSB((kc + 1) & 1);
            cp_async16(wd + doff,      gW + k1);
            cp_async16(wd + doff + 16, gW + k1 + 8);
            asm volatile("cp.async.commit_group;" ::: "memory");
        }

#pragma unroll
        for (int ks = 0; ks < 2; ++ks) {
            const uint32_t ko = (uint32_t)ks * 32;
            uint32_t BH[2][4];
            ldsm4(BH[0], sw + bBase[0] + ko);
            ldsm4(BH[1], sw + bBase[1] + ko);
#pragma unroll
            for (int mf = 0; mf < 4; ++mf) {
                uint32_t AH[4];
                ldsm4(AH, sx + aBase[mf] + ko);
#pragma unroll
                for (int nf = 0; nf < 4; ++nf)
                    MMA_F16(acc[mf][nf], AH[0], AH[1], AH[2], AH[3],
                            BH[nf >> 1][nf & 1], BH[nf >> 1][(nf & 1) + 2]);
            }
        }

        if (has_next) {
            uint32_t hv[8];
#pragma unroll
            for (int j = 0; j < 4; ++j) {
                hv[2 * j]     = f16pack(av[j].x, av[j].y);
                hv[2 * j + 1] = f16pack(av[j].z, av[j].w);
            }
            char* xd = smem + XS_CH(kc + 1);
            *(uint4*)(xd + doff)      = make_uint4(hv[0], hv[1], hv[2], hv[3]);
            *(uint4*)(xd + doff + 16) = make_uint4(hv[4], hv[5], hv[6], hv[7]);
            asm volatile("cp.async.wait_group 0;" ::: "memory");
        }
        __syncthreads();
    }

    // ---- partial scores over this CTA's 128 cols ----
    float partA[4] = {0.f, 0.f, 0.f, 0.f};
    float partB[4] = {0.f, 0.f, 0.f, 0.f};
#pragma unroll
    for (int mf = 0; mf < 4; ++mf) {
#pragma unroll
        for (int nf = 0; nf < 4; ++nf) {
            const int c0 = warp_n * 32 + nf * 8 + 2 * t;
            const float w20 = w2s[c0], w21 = w2s[c0 + 1];
            const float bb0 = b1s[c0], bb1 = b1s[c0 + 1];
            partA[mf] += fast_tanh(acc[mf][nf][0] + bb0) * w20
                       + fast_tanh(acc[mf][nf][1] + bb1) * w21;
            partB[mf] += fast_tanh(acc[mf][nf][2] + bb0) * w20
                       + fast_tanh(acc[mf][nf][3] + bb1) * w21;
        }
    }
#pragma unroll
    for (int mf = 0; mf < 4; ++mf) {
        partA[mf] += __shfl_xor_sync(0xffffffffu, partA[mf], 1);
        partA[mf] += __shfl_xor_sync(0xffffffffu, partA[mf], 2);
        partB[mf] += __shfl_xor_sync(0xffffffffu, partB[mf], 1);
        partB[mf] += __shfl_xor_sync(0xffffffffu, partB[mf], 2);
    }
    if (t == 0) {
#pragma unroll
        for (int mf = 0; mf < 4; ++mf) {
            atomicAdd(&score_s[warp_m * 64 + mf * 16 + g], partA[mf]);
            atomicAdd(&score_s[warp_m * 64 + mf * 16 + g + 8], partB[mf]);
        }
    }
    __syncthreads();

    // ---- exchange partial scores with peer CTA via DSMEM ----
    CLUSTER_SYNC();
    if (tid < 128) {
        float peer = dsmem_ld_f32(sb + SC_OFF + (uint32_t)tid * 4, (uint32_t)(rank ^ 1));
        float tot = score_s[tid] + peer;
        float e = __expf(fminf(tot, 10.f));
        __half eh = __float2half(e);
        e16[tid] = eh;
        atomicAdd(&esum[tid >> 6], __half2float(eh));
    }
    __syncthreads();

    // ---- pooled partials: this CTA pools h-cols [rank*128, rank*128+128) ----
    {
        const int vw = rank * 8 + warp;           // virtual warp 0..15 -> 16 h-cols
        const int h0 = vw * 16;
        const int grpIdx = lane >> 3;
        const uint32_t bAddr0 = sb + XS_CH(vw >> 1)
            + (uint32_t)(((vw & 1) * 16 + (grpIdx >> 1) * 8) * 2)
            + (uint32_t)(((grpIdx & 1) * 8 + (lane & 7)) * ROWB);

        float pc0[4] = {0.f, 0.f, 0.f, 0.f};
        float pc1[4] = {0.f, 0.f, 0.f, 0.f};
#pragma unroll
        for (int ks = 0; ks < 8; ++ks) {
            const int sel = ks >> 2;   // graph owning rows 16ks..16ks+15
            uint32_t a0 = 0, a2 = 0;
            if (g == sel) {
                a0 = *(const uint32_t*)&e16[16 * ks + 2 * t];
                a2 = *(const uint32_t*)&e16[16 * ks + 2 * t + 8];
            }
            uint32_t rb[4];
            ldsm4t(rb, bAddr0 + (uint32_t)ks * 16 * ROWB);
            MMA_F16(pc0, a0, 0u, a2, 0u, rb[0], rb[1]);
            MMA_F16(pc1, a0, 0u, a2, 0u, rb[2], rb[3]);
        }
        if (g < 2) {
            float* o0 = out + (size_t)(gbase + g) * H + h0 + 2 * t;
            o0[0] = pc0[0]; o0[1] = pc0[1];
            o0[8] = pc1[0]; o0[9] = pc1[1];
        }
    }
    if (rank == 0 && tid < 2) d_gsum[gbase + tid] = esum[tid];

    // keep both CTAs alive until all DSMEM reads are done
    CLUSTER_SYNC();
}

// ---- normalize: out[g][h] /= sum_e over g's chunk ----
__global__ void normalize_kernel(float* __restrict__ out)
{
    const int c = blockIdx.x;      // chunk
    const int tid = threadIdx.x;   // 256
    __shared__ float ssum;
    if (tid < 32) {
        float v = d_gsum[c * 32 + tid];
#pragma unroll
        for (int o = 16; o; o >>= 1) v += __shfl_xor_sync(0xffffffffu, v, o);
        if (tid == 0) ssum = v;
    }
    __syncthreads();
    const float inv = 1.f / ssum;
#pragma unroll 4
    for (int i = 0; i < 32; ++i) {
        size_t idx = ((size_t)(c * 32 + i)) * H + tid;
        out[idx] *= inv;
    }
}

// ---------------- launch ----------------
extern "C" void kernel_launch(void* const* d_in, const int* in_sizes, int n_in,
                              void* d_out, int out_size)
{
    const float* x  = (const float*)d_in[0];
    const float* W1 = (const float*)d_in[2];
    const float* b1 = (const float*)d_in[3];
    const float* W2 = (const float*)d_in[4];
    float* out = (float*)d_out;

    cudaFuncSetAttribute(mega_kernel,
                         cudaFuncAttributeMaxDynamicSharedMemorySize, SMEM_TOTAL);

    prep_w_kernel<<<H, H>>>(W1);
    mega_kernel<<<(NODES / TM) * 2, 256, SMEM_TOTAL>>>(x, b1, W2, out);
    normalize_kernel<<<NCHUNK, 256>>>(out);
}